// round 16
// baseline (speedup 1.0000x reference)
#include <cuda_runtime.h>
#include <math.h>

#define N_NODES 8192
#define F_IN 128
#define F_OUT 64
#define NEG_SLOPE 0.2f
#define VERY_SMALL 1000000000000.0f
#define LOG2E 1.4426950408889634f
#define SD_BLOCKS 128
#define ROWS_PER_SD_BLOCK (N_NODES / SD_BLOCKS)   // 64 (8 per warp)

__device__ float g_s[N_NODES];
__device__ float g_d[N_NODES];
__device__ float g_bmax[SD_BLOCKS];   // per-block max of d

// Kernel A: fused prep + sd + per-block d-max. 128 blocks (ONE wave) x 256 thr,
// 64 rows/block, 8 rows/warp, front-batched loads. Signals PDL dependents
// immediately; they idle at their wait (no traffic — R11 lesson).
__global__ __launch_bounds__(256) void sd_kernel(const float* __restrict__ h,
                                                 const float* __restrict__ w,
                                                 const float* __restrict__ a) {
    __shared__ float sa[F_IN];
    __shared__ float sws[F_IN];
    __shared__ float swd[F_IN];
    __shared__ float wmax[8];
    const int t = threadIdx.x;
    const int warp = t >> 5;
    const int lane = t & 31;

    asm volatile("griddepcontrol.launch_dependents;" ::: "memory");

    if (t < F_IN) sa[t] = a[t];
    __syncthreads();

    // ws[k]/wd[k]: thread t owns float4 f=t+256r of w (coalesced); the 16
    // threads sharing k=f>>4 shfl-subreduce deterministically.
    const float4* w4 = reinterpret_cast<const float4*>(w);
    const int j = (t & 15) * 4;
    #pragma unroll
    for (int r = 0; r < 8; ++r) {
        float4 v = w4[t + r * 256];
        float ps = v.x * sa[j] + v.y * sa[j + 1] + v.z * sa[j + 2] + v.w * sa[j + 3];
        float pd = v.x * sa[64 + j] + v.y * sa[64 + j + 1] + v.z * sa[64 + j + 2] + v.w * sa[64 + j + 3];
        #pragma unroll
        for (int o = 8; o > 0; o >>= 1) {
            ps += __shfl_xor_sync(0xffffffffu, ps, o);
            pd += __shfl_xor_sync(0xffffffffu, pd, o);
        }
        if ((t & 15) == 0) {
            int k = r * 16 + (t >> 4);
            sws[k] = ps;
            swd[k] = pd;
        }
    }
    __syncthreads();

    // 8 rows per warp: front-batched loads, interleaved shfl chains.
    const int base = blockIdx.x * ROWS_PER_SD_BLOCK + warp * 8;
    const float4 wsv = reinterpret_cast<const float4*>(sws)[lane];
    const float4 wdv = reinterpret_cast<const float4*>(swd)[lane];
    const float4* h4 = reinterpret_cast<const float4*>(h);

    float4 hv[8];
    #pragma unroll
    for (int r = 0; r < 8; ++r)
        hv[r] = h4[(size_t)(base + r) * (F_IN / 4) + lane];

    float s[8], d[8];
    #pragma unroll
    for (int r = 0; r < 8; ++r) {
        s[r] = hv[r].x * wsv.x + hv[r].y * wsv.y + hv[r].z * wsv.z + hv[r].w * wsv.w;
        d[r] = hv[r].x * wdv.x + hv[r].y * wdv.y + hv[r].z * wdv.z + hv[r].w * wdv.w;
    }
    #pragma unroll
    for (int o = 16; o > 0; o >>= 1) {
        #pragma unroll
        for (int r = 0; r < 8; ++r) {
            s[r] += __shfl_xor_sync(0xffffffffu, s[r], o);
            d[r] += __shfl_xor_sync(0xffffffffu, d[r], o);
        }
    }
    if (lane == 0) {
        float dmax = -INFINITY;
        #pragma unroll
        for (int r = 0; r < 8; ++r) {
            g_s[base + r] = s[r];
            g_d[base + r] = d[r];
            dmax = fmaxf(dmax, d[r]);
        }
        wmax[warp] = dmax;
    }
    __syncthreads();
    if (t == 0) {
        float m = wmax[0];
        #pragma unroll
        for (int k = 1; k < 8; ++k) m = fmaxf(m, wmax[k]);
        g_bmax[blockIdx.x] = m;
    }
}

__device__ __forceinline__ float block_reduce_sum(float v, float* red) {
    #pragma unroll
    for (int o = 16; o > 0; o >>= 1)
        v += __shfl_xor_sync(0xffffffffu, v, o);
    int warp = threadIdx.x >> 5;
    if ((threadIdx.x & 31) == 0) red[warp] = v;
    __syncthreads();
    if (warp == 0) {
        float x = (threadIdx.x < 8) ? red[threadIdx.x] : 0.f;
        #pragma unroll
        for (int o = 4; o > 0; o >>= 1)
            x += __shfl_xor_sync(0xffffffffu, x, o);
        if (threadIdx.x == 0) red[0] = x;
    }
    __syncthreads();
    return red[0];
}

// Kernel B: proven softmax body (wait at top, idle until sd visible), with
// the exp folded to one FMA + MUFU per element:
//   exp(v - M) = exp2(v*LOG2E - M*LOG2E), and lrelu(x) = fmax(x, 0.2x).
__global__ __launch_bounds__(256) void softmax_kernel(const float* __restrict__ adj,
                                                      float* __restrict__ out) {
    __shared__ float red[8];
    const int i = blockIdx.x;
    const int t = threadIdx.x;
    const int lane = t & 31;

    asm volatile("griddepcontrol.wait;" ::: "memory");

    const float si = g_s[i];

    // Warp-parallel D fold: 128 bmax = 32 float4, one per lane, 5 shfls.
    float4 mm = __ldg(&reinterpret_cast<const float4*>(g_bmax)[lane]);
    float D = fmaxf(fmaxf(mm.x, mm.y), fmaxf(mm.z, mm.w));
    #pragma unroll
    for (int o = 16; o > 0; o >>= 1)
        D = fmaxf(D, __shfl_xor_sync(0xffffffffu, D, o));
    float M = si + D;
    M = fmaxf(M, NEG_SLOPE * M);          // lrelu(M): M is the row's upper bound
    const float MLOG2E = M * LOG2E;

    const float4* ap = reinterpret_cast<const float4*>(adj + (size_t)i * N_NODES);
    const float4* dp = reinterpret_cast<const float4*>(g_d);

    float4 e[8];
    float lsum = 0.f;
    #pragma unroll
    for (int k = 0; k < 8; ++k) {
        const int c = t + k * 256;
        float4 av = __ldcs(&ap[c]);   // adj read once: evict-first
        float4 dv = __ldg(&dp[c]);    // 32 KB, reused by all CTAs: L1-cached
        float v0 = si + dv.x; v0 = fmaxf(v0, NEG_SLOPE * v0); v0 = (av.x > 0.f) ? v0 : -VERY_SMALL;
        float v1 = si + dv.y; v1 = fmaxf(v1, NEG_SLOPE * v1); v1 = (av.y > 0.f) ? v1 : -VERY_SMALL;
        float v2 = si + dv.z; v2 = fmaxf(v2, NEG_SLOPE * v2); v2 = (av.z > 0.f) ? v2 : -VERY_SMALL;
        float v3 = si + dv.w; v3 = fmaxf(v3, NEG_SLOPE * v3); v3 = (av.w > 0.f) ? v3 : -VERY_SMALL;
        e[k].x = exp2f(__fmaf_rn(v0, LOG2E, -MLOG2E));
        e[k].y = exp2f(__fmaf_rn(v1, LOG2E, -MLOG2E));
        e[k].z = exp2f(__fmaf_rn(v2, LOG2E, -MLOG2E));
        e[k].w = exp2f(__fmaf_rn(v3, LOG2E, -MLOG2E));
        lsum += (e[k].x + e[k].y) + (e[k].z + e[k].w);
    }
    const float ssum = block_reduce_sum(lsum, red);
    const float inv = 1.0f / ssum;

    float4* op = reinterpret_cast<float4*>(out + (size_t)i * N_NODES);
    #pragma unroll
    for (int k = 0; k < 8; ++k) {
        const int c = t + k * 256;
        float4 o = e[k];
        o.x *= inv; o.y *= inv; o.z *= inv; o.w *= inv;
        __stcs(&op[c], o);   // out never re-read: streaming store
    }
}

extern "C" void kernel_launch(void* const* d_in, const int* in_sizes, int n_in,
                              void* d_out, int out_size) {
    const float* h   = (const float*)d_in[0];  // [8192,128]
    const float* adj = (const float*)d_in[1];  // [8192,8192]
    const float* w   = (const float*)d_in[2];  // [128,64]
    const float* a   = (const float*)d_in[3];  // [128,1]
    float* out = (float*)d_out;

    sd_kernel<<<SD_BLOCKS, 256>>>(h, w, a);

    // PDL: softmax CTAs pre-launch under sd_kernel; they idle at the wait
    // (no memory traffic) until sd's results are visible.
    cudaLaunchConfig_t cfg = {};
    cfg.gridDim = dim3(N_NODES, 1, 1);
    cfg.blockDim = dim3(256, 1, 1);
    cfg.dynamicSmemBytes = 0;
    cudaLaunchAttribute attrs[1];
    attrs[0].id = cudaLaunchAttributeProgrammaticStreamSerialization;
    attrs[0].val.programmaticStreamSerializationAllowed = 1;
    cfg.attrs = attrs;
    cfg.numAttrs = 1;
    cudaLaunchKernelEx(&cfg, softmax_kernel, adj, out);
}

// round 17
// speedup vs baseline: 1.0981x; 1.0981x over previous
#include <cuda_runtime.h>
#include <math.h>

#define N_NODES 8192
#define F_IN 128
#define F_OUT 64
#define NEG_SLOPE 0.2f
#define VERY_SMALL 1000000000000.0f
#define SD_BLOCKS 256
#define ROWS_PER_SD_BLOCK (N_NODES / SD_BLOCKS)   // 32 (4 per warp)

__device__ float g_s[N_NODES];
__device__ float g_d[N_NODES];
__device__ float g_bmax[SD_BLOCKS];   // per-block max of d

// Kernel A: fused prep + sd + per-block d-max. 256 blocks x 256 thr, 32 rows.
// Signals PDL dependents immediately; they idle at their wait (no traffic).
__global__ __launch_bounds__(256) void sd_kernel(const float* __restrict__ h,
                                                 const float* __restrict__ w,
                                                 const float* __restrict__ a) {
    __shared__ float sa[F_IN];
    __shared__ float sws[F_IN];
    __shared__ float swd[F_IN];
    __shared__ float wmax[8];
    const int t = threadIdx.x;
    const int warp = t >> 5;
    const int lane = t & 31;

    // Dependent grid may start launching now; its CTAs block at wait
    // before issuing any memory traffic, so no interference (R11 lesson).
    asm volatile("griddepcontrol.launch_dependents;" ::: "memory");

    if (t < F_IN) sa[t] = a[t];
    __syncthreads();

    // ws[k]/wd[k]: thread t owns float4 f=t+256r of w (coalesced); the 16
    // threads sharing k=f>>4 shfl-subreduce deterministically.
    const float4* w4 = reinterpret_cast<const float4*>(w);
    const int j = (t & 15) * 4;
    #pragma unroll
    for (int r = 0; r < 8; ++r) {
        float4 v = w4[t + r * 256];
        float ps = v.x * sa[j] + v.y * sa[j + 1] + v.z * sa[j + 2] + v.w * sa[j + 3];
        float pd = v.x * sa[64 + j] + v.y * sa[64 + j + 1] + v.z * sa[64 + j + 2] + v.w * sa[64 + j + 3];
        #pragma unroll
        for (int o = 8; o > 0; o >>= 1) {
            ps += __shfl_xor_sync(0xffffffffu, ps, o);
            pd += __shfl_xor_sync(0xffffffffu, pd, o);
        }
        if ((t & 15) == 0) {
            int k = r * 16 + (t >> 4);
            sws[k] = ps;
            swd[k] = pd;
        }
    }
    __syncthreads();

    // 4 rows per warp, front-batched loads, interleaved shfl chains.
    const int base = blockIdx.x * ROWS_PER_SD_BLOCK + warp * 4;
    const float4 wsv = reinterpret_cast<const float4*>(sws)[lane];
    const float4 wdv = reinterpret_cast<const float4*>(swd)[lane];
    const float4* h4 = reinterpret_cast<const float4*>(h);

    float4 hv[4];
    #pragma unroll
    for (int r = 0; r < 4; ++r)
        hv[r] = h4[(size_t)(base + r) * (F_IN / 4) + lane];

    float s[4], d[4];
    #pragma unroll
    for (int r = 0; r < 4; ++r) {
        s[r] = hv[r].x * wsv.x + hv[r].y * wsv.y + hv[r].z * wsv.z + hv[r].w * wsv.w;
        d[r] = hv[r].x * wdv.x + hv[r].y * wdv.y + hv[r].z * wdv.z + hv[r].w * wdv.w;
    }
    #pragma unroll
    for (int o = 16; o > 0; o >>= 1) {
        #pragma unroll
        for (int r = 0; r < 4; ++r) {
            s[r] += __shfl_xor_sync(0xffffffffu, s[r], o);
            d[r] += __shfl_xor_sync(0xffffffffu, d[r], o);
        }
    }
    if (lane == 0) {
        float dmax = -INFINITY;
        #pragma unroll
        for (int r = 0; r < 4; ++r) {
            g_s[base + r] = s[r];
            g_d[base + r] = d[r];
            dmax = fmaxf(dmax, d[r]);
        }
        wmax[warp] = dmax;
    }
    __syncthreads();
    if (t == 0) {
        float m = wmax[0];
        #pragma unroll
        for (int k = 1; k < 8; ++k) m = fmaxf(m, wmax[k]);
        g_bmax[blockIdx.x] = m;
    }
}

// Single-barrier block reduce: warp partials -> ONE bar.sync -> every thread
// folds the 8 partials itself (smem broadcast reads, conflict-free).
__device__ __forceinline__ float block_reduce_sum_1bar(float v, float* red) {
    #pragma unroll
    for (int o = 16; o > 0; o >>= 1)
        v += __shfl_xor_sync(0xffffffffu, v, o);
    if ((threadIdx.x & 31) == 0) red[threadIdx.x >> 5] = v;
    __syncthreads();
    float x = (red[0] + red[1]) + (red[2] + red[3]);
    float y = (red[4] + red[5]) + (red[6] + red[7]);
    return x + y;
}

// Kernel B: R15 softmax body, unchanged hot loop; only the reduce lost a barrier.
__global__ __launch_bounds__(256) void softmax_kernel(const float* __restrict__ adj,
                                                      float* __restrict__ out) {
    __shared__ float red[8];
    const int i = blockIdx.x;
    const int t = threadIdx.x;
    const int lane = t & 31;

    // PDL: block until sd_kernel's writes (g_s/g_d/g_bmax) are visible.
    asm volatile("griddepcontrol.wait;" ::: "memory");

    const float si = g_s[i];

    // Warp-parallel D fold: 256 bmax = 64 float4, 2 per lane, 5 shfls.
    const float4* bm4 = reinterpret_cast<const float4*>(g_bmax);
    float4 m0 = __ldg(&bm4[lane]);
    float4 m1 = __ldg(&bm4[lane + 32]);
    float D = fmaxf(fmaxf(fmaxf(m0.x, m0.y), fmaxf(m0.z, m0.w)),
                    fmaxf(fmaxf(m1.x, m1.y), fmaxf(m1.z, m1.w)));
    #pragma unroll
    for (int o = 16; o > 0; o >>= 1)
        D = fmaxf(D, __shfl_xor_sync(0xffffffffu, D, o));
    float M = si + D;
    M = M >= 0.f ? M : NEG_SLOPE * M;

    const float4* ap = reinterpret_cast<const float4*>(adj + (size_t)i * N_NODES);
    const float4* dp = reinterpret_cast<const float4*>(g_d);

    float4 e[8];
    float lsum = 0.f;
    #pragma unroll
    for (int k = 0; k < 8; ++k) {
        const int c = t + k * 256;
        float4 av = __ldcs(&ap[c]);   // adj read once: evict-first
        float4 dv = __ldg(&dp[c]);    // 32 KB, reused by all CTAs: L1-cached
        float v0 = si + dv.x; v0 = v0 >= 0.f ? v0 : NEG_SLOPE * v0; v0 = (av.x > 0.f) ? v0 : -VERY_SMALL;
        float v1 = si + dv.y; v1 = v1 >= 0.f ? v1 : NEG_SLOPE * v1; v1 = (av.y > 0.f) ? v1 : -VERY_SMALL;
        float v2 = si + dv.z; v2 = v2 >= 0.f ? v2 : NEG_SLOPE * v2; v2 = (av.z > 0.f) ? v2 : -VERY_SMALL;
        float v3 = si + dv.w; v3 = v3 >= 0.f ? v3 : NEG_SLOPE * v3; v3 = (av.w > 0.f) ? v3 : -VERY_SMALL;
        e[k].x = __expf(v0 - M);
        e[k].y = __expf(v1 - M);
        e[k].z = __expf(v2 - M);
        e[k].w = __expf(v3 - M);
        lsum += (e[k].x + e[k].y) + (e[k].z + e[k].w);
    }
    const float ssum = block_reduce_sum_1bar(lsum, red);
    const float inv = 1.0f / ssum;

    float4* op = reinterpret_cast<float4*>(out + (size_t)i * N_NODES);
    #pragma unroll
    for (int k = 0; k < 8; ++k) {
        const int c = t + k * 256;
        float4 o = e[k];
        o.x *= inv; o.y *= inv; o.z *= inv; o.w *= inv;
        __stcs(&op[c], o);   // out never re-read: streaming store
    }
}

extern "C" void kernel_launch(void* const* d_in, const int* in_sizes, int n_in,
                              void* d_out, int out_size) {
    const float* h   = (const float*)d_in[0];  // [8192,128]
    const float* adj = (const float*)d_in[1];  // [8192,8192]
    const float* w   = (const float*)d_in[2];  // [128,64]
    const float* a   = (const float*)d_in[3];  // [128,1]
    float* out = (float*)d_out;

    sd_kernel<<<SD_BLOCKS, 256>>>(h, w, a);

    // PDL: softmax CTAs pre-launch under sd_kernel; they idle at the wait
    // (no memory traffic) until sd's results are visible.
    cudaLaunchConfig_t cfg = {};
    cfg.gridDim = dim3(N_NODES, 1, 1);
    cfg.blockDim = dim3(256, 1, 1);
    cfg.dynamicSmemBytes = 0;
    cudaLaunchAttribute attrs[1];
    attrs[0].id = cudaLaunchAttributeProgrammaticStreamSerialization;
    attrs[0].val.programmaticStreamSerializationAllowed = 1;
    cfg.attrs = attrs;
    cfg.numAttrs = 1;
    cudaLaunchKernelEx(&cfg, softmax_kernel, adj, out);
}